// round 15
// baseline (speedup 1.0000x reference)
#include <cuda_runtime.h>
#include <cuda_fp16.h>
#include <math.h>

// T=4096, B=4, S=16 -> 64 sequences; F=64, CH=97 (16 B + 16 C + 1 A + 64 X),
// K=5, CHUNK=64, 64 chunks, N_state=16, P=64 (collapsed via red_w projection).
// R10 base (persistent fp16-MMA conv, Gram in MMA regs, 2 blocks/SM, fp16 g_C)
// + ldmatrix fragment loads in the conv inner loop (only change vs R10).

#define NSEQ   64
#define T_TOT  4096
#define NCHUNK 64

__device__ __forceinline__ float clip20(float v) { return fminf(fmaxf(v, -20.f), 20.f); }

// ---------- device scratch ----------
__device__ __align__(16) __half g_wB16[104 * 328];  // [ch][kk=k*64+f] fp16, zero-padded
__device__ __align__(16) __half g_Ch[T_TOT * NSEQ * 16]; // [t][n][16] fp16
__device__ float g_cum[T_TOT * NSEQ];               // [t][n]
__device__ float g_base[T_TOT * NSEQ];              // [t][n]
__device__ float g_sr[NSEQ * NCHUNK * 16];
__device__ float g_dch[NSEQ * NCHUNK];
__device__ float g_hr[NCHUNK * NSEQ * 16];          // [c][n][16]

// ---------- K0: build fp16 weight matrix ----------
__global__ void k_wt(const float* __restrict__ w) {
    int i = blockIdx.x * blockDim.x + threadIdx.x;
    if (i < 104 * 328) {
        int ch = i / 328, kk = i % 328;
        int k = kk >> 6, f = kk & 63;
        float v = (ch < 97 && kk < 320) ? w[ch * 320 + f * 5 + k] : 0.f;
        g_wB16[i] = __float2half(v);
    }
}

// ---------- shared layout (float offsets; fp16 regions via casts) ----------
#define WB16_O  0          // 104*328 halves = 17056 floats
#define XT_O    17056      // 68*72 halves = 2448 floats (x fp16, [lt][f] stride 72)
#define SX_O    19504      // 64*65 fp32 X channels
#define SC_O    23664      // 64*17 fp32
#define SB_O    24752      // 64*17 fp32
#define SB16_O  25840      // 64*18 halves = 576 floats
#define SC16_O  26416      // 576
#define SA_O    26992      // 64
#define SCOEF_O 27056
#define SCUM_O  27120
#define SWS_O   27184
#define SDEC_O  27248
#define SDX_O   27312
#define SYD_O   27376      // 64
#define SSR_O   27440      // 64
#define SRW_O   27504
#define SPW_O   27568
#define SCB_O   27632      // 104
#define SMEMF   27736      // 110944 bytes -> 2 blocks/SM

#define MMA16(d, a0,a1,a2,a3, b0,b1) \
    asm volatile("mma.sync.aligned.m16n8k16.row.col.f32.f16.f16.f32 " \
        "{%0,%1,%2,%3},{%4,%5,%6,%7},{%8,%9},{%0,%1,%2,%3};" \
        : "+f"((d)[0]), "+f"((d)[1]), "+f"((d)[2]), "+f"((d)[3]) \
        : "r"(a0), "r"(a1), "r"(a2), "r"(a3), "r"(b0), "r"(b1))

#define LDSM4(r0,r1,r2,r3, addr) \
    asm volatile("ldmatrix.sync.aligned.m8n8.x4.shared.b16 {%0,%1,%2,%3},[%4];" \
        : "=r"(r0), "=r"(r1), "=r"(r2), "=r"(r3) : "r"(addr))

// ---------- K1: persistent ----------
__global__ __launch_bounds__(256, 2) void k_main(
    const float* __restrict__ x,
    const float* __restrict__ conv_b,
    const float* __restrict__ pass_w,
    const float* __restrict__ pass_b,
    const float* __restrict__ red_w,
    const float* __restrict__ red_b,
    const float* __restrict__ dt_param)
{
    extern __shared__ float sm[];
    const int tid  = threadIdx.x;
    const int lane = tid & 31;
    const int wid  = tid >> 5;          // 8 warps
    const unsigned smem_b = (unsigned)__cvta_generic_to_shared(sm);

    // weight tile (fp16) + small params: ONCE per persistent block
    for (int i = tid; i < 17056 / 4; i += 256)
        ((float4*)sm)[i] = ((const float4*)g_wB16)[i];
    if (tid < 64) { sm[SRW_O + tid] = red_w[tid]; sm[SPW_O + tid] = pass_w[tid]; }
    if (tid >= 64 && tid < 168) sm[SCB_O + (tid - 64)] = (tid - 64 < 97) ? conv_b[tid - 64] : 0.f;
    const float dt = log1pf(expf(dt_param[0])) + 0.01f;
    const float pb = pass_b[0], rb = red_b[0];
    __syncthreads();

    // conv roles: mtile = wid&3 (16 t rows), nhalf = wid>>2
    const int mtile = wid & 3;
    const int nhalf = wid >> 2;
    const int nq    = nhalf ? 6 : 7;
    const int qb    = nhalf * 7;
    const int lc = lane & 3, lr = lane >> 2;

    // ldmatrix lane->address components (reproduces scalar fragment layout)
    const int rowA = (lane & 7) + (((lane >> 3) & 1) << 3);
    const int colA = (lane >> 4) << 3;
    const int chB  = (lane & 7) + ((lane >> 4) << 3);
    const int colB = ((lane >> 3) & 1) << 3;

    const unsigned xtA0 = smem_b + XT_O * 4 + (mtile * 16 * 72 + rowA * 72 + colA) * 2;
    const unsigned wbB0 = smem_b + ((nhalf * 56 + chB) * 328 + colB) * 2;
    const unsigned wbB2 = smem_b + ((48 + (lane & 7)) * 328 + (((lane >> 3) & 1) << 3)) * 2;

    __half* xt = (__half*)(sm + XT_O);

    for (int u = blockIdx.x; u < NSEQ * NCHUNK; u += gridDim.x) {
        const int n = u & 63, chunk = u >> 6;
        const int b = n >> 4, s = n & 15;
        const int t0g = chunk * 64 - 4;

        // load x -> fp16 tile
        for (int i = tid; i < 68 * 64; i += 256) {
            int lt = i >> 6, f = i & 63;
            int tg = t0g + lt;
            float v = (tg >= 0) ? x[((tg * 4 + b) * 16 + s) * 64 + f] : 0.f;
            xt[lt * 72 + f] = __float2half(v);
        }
        __syncthreads();

        // ---- conv MMA (fp16 m16n8k16, ldmatrix fragments): 20 k-steps ----
        float acc[7][4];
#pragma unroll
        for (int q = 0; q < 7; ++q)
#pragma unroll
            for (int e = 0; e < 4; ++e) acc[q][e] = 0.f;

#pragma unroll
        for (int ks = 0; ks < 20; ++ks) {
            const int sh = ks >> 2, f0 = (ks & 3) * 16;
            unsigned a0, a1, a2, a3;
            LDSM4(a0, a1, a2, a3, xtA0 + (sh * 72 + f0) * 2);
#pragma unroll
            for (int p = 0; p < 3; ++p) {
                unsigned b0, b1, b2, b3;
                LDSM4(b0, b1, b2, b3, wbB0 + ks * 32 + p * (16 * 328 * 2));
                MMA16(acc[2 * p],     a0, a1, a2, a3, b0, b1);
                MMA16(acc[2 * p + 1], a0, a1, a2, a3, b2, b3);
            }
            if (nhalf == 0) {
                unsigned b0, b1;
                asm volatile("ldmatrix.sync.aligned.m8n8.x2.shared.b16 {%0,%1},[%2];"
                             : "=r"(b0), "=r"(b1) : "r"(wbB2 + ks * 32));
                MMA16(acc[6], a0, a1, a2, a3, b0, b1);
            }
        }

        // ---- epilogue: bias + (v + sigmoid(v)) + scatter ----
        {
            __half* b16 = (__half*)(sm + SB16_O);
            __half* c16 = (__half*)(sm + SC16_O);
#pragma unroll
            for (int qq = 0; qq < 7; ++qq) {
                if (qq < nq) {
                    const int ch0 = (qb + qq) * 8 + 2 * lc;
                    const int t0r = mtile * 16 + lr;
#pragma unroll
                    for (int e = 0; e < 4; ++e) {
                        const int ch = ch0 + (e & 1);
                        const int t  = t0r + (e >> 1) * 8;
                        float v = acc[qq][e] + sm[SCB_O + ch];
                        float uu = v + __fdividef(1.f, 1.f + __expf(-v));
                        if (ch < 16) {
                            sm[SB_O + t * 17 + ch] = uu;
                            b16[t * 18 + ch] = __float2half(uu);
                        } else if (ch < 32) {
                            sm[SC_O + t * 17 + (ch - 16)] = uu;
                            c16[t * 18 + (ch - 16)] = __float2half(uu);
                        } else if (ch == 32) {
                            float A  = -fabsf(uu);
                            float la = dt * A;
                            sm[SA_O + t]    = la;
                            sm[SCOEF_O + t] = (__expf(la) - 1.f) / (A + 1e-9f);
                        } else if (ch < 97) sm[SX_O + t * 65 + (ch - 33)] = uu;
                    }
                }
            }
        }
        __syncthreads();

        // ---- phase 1: scan | xr/Dx | C export | Gram MMA (regs persist) ----
        float g[8][4];
        if (tid < 32) {
            float v0 = sm[SA_O + tid], v1 = sm[SA_O + 32 + tid];
#pragma unroll
            for (int o = 1; o < 32; o <<= 1) {
                float a0 = __shfl_up_sync(0xffffffffu, v0, o);
                float a1 = __shfl_up_sync(0xffffffffu, v1, o);
                if (tid >= o) { v0 += a0; v1 += a1; }
            }
            float tot0  = __shfl_sync(0xffffffffu, v0, 31);
            float cum_b = v1 + tot0;
            float tot   = __shfl_sync(0xffffffffu, cum_b, 31);
            sm[SCUM_O + tid]      = v0;
            sm[SCUM_O + 32 + tid] = cum_b;
            sm[SDEC_O + tid]      = __expf(clip20(tot - v0));
            sm[SDEC_O + 32 + tid] = __expf(clip20(tot - cum_b));
            if (tid == 31) g_dch[n * 64 + chunk] = __expf(clip20(tot));
        } else if (tid < 96) {
            int t = tid - 32;
            float xr = 0.f;
#pragma unroll
            for (int p = 0; p < 64; ++p) xr = fmaf(sm[SX_O + t * 65 + p], sm[SRW_O + p], xr);
            const __half2* xrow = (const __half2*)(xt + (t + 4) * 72);
            float dx = pb;
#pragma unroll
            for (int f2 = 0; f2 < 32; ++f2) {
                float2 v = __half22float2(xrow[f2]);
                dx = fmaf(v.x, sm[SPW_O + 2 * f2], dx);
                dx = fmaf(v.y, sm[SPW_O + 2 * f2 + 1], dx);
            }
            sm[SWS_O + t] = xr * sm[SCOEF_O + t];
            sm[SDX_O + t] = dx;
        } else if (tid < 128) {
            const __half* c16 = (const __half*)(sm + SC16_O);
            for (int idx = tid - 96; idx < 1024; idx += 32) {
                int l = idx >> 4, i = idx & 15;
                g_Ch[(((chunk * 64 + l) * 64) + n) * 16 + i] = c16[l * 18 + i];
            }
        } else {
            // Gram: G[l][m] = sum_i C[l][i]*B[m][i]; warp w = l-tile, 8 m-tiles
            const int w = wid - 4;
            const __half* c16 = (const __half*)(sm + SC16_O);
            const __half* b16 = (const __half*)(sm + SB16_O);
            const __half* capt = c16 + (w * 16 + lr) * 18 + 2 * lc;
            unsigned a0 = *(const unsigned*)(capt);
            unsigned a1 = *(const unsigned*)(capt + 8 * 18);
            unsigned a2 = *(const unsigned*)(capt + 8);
            unsigned a3 = *(const unsigned*)(capt + 8 * 18 + 8);
#pragma unroll
            for (int q = 0; q < 8; ++q) {
                const __half* bq = b16 + (q * 8 + lr) * 18 + 2 * lc;
                unsigned b0 = *(const unsigned*)(bq);
                unsigned b1 = *(const unsigned*)(bq + 8);
                g[q][0] = g[q][1] = g[q][2] = g[q][3] = 0.f;
                MMA16(g[q], a0, a1, a2, a3, b0, b1);
            }
        }
        __syncthreads();

        // ---- phase 2: y_diag from Gram registers | state partials ----
        if (tid >= 128) {
            const int w = wid - 4;
            const int l0 = w * 16 + lr, l1 = l0 + 8;
            const float cl0 = sm[SCUM_O + l0], cl1 = sm[SCUM_O + l1];
            float acc0 = 0.f, acc1 = 0.f;
#pragma unroll
            for (int q = 0; q < 8; ++q) {
                const int m0 = q * 8 + 2 * lc, m1 = m0 + 1;
                const float w0 = sm[SWS_O + m0], w1 = sm[SWS_O + m1];
                const float c0 = sm[SCUM_O + m0], c1 = sm[SCUM_O + m1];
                float e00 = (m0 <= l0) ? __expf(clip20(cl0 - c0)) : 0.f;
                float e01 = (m1 <= l0) ? __expf(clip20(cl0 - c1)) : 0.f;
                float e10 = (m0 <= l1) ? __expf(clip20(cl1 - c0)) : 0.f;
                float e11 = (m1 <= l1) ? __expf(clip20(cl1 - c1)) : 0.f;
                acc0 = fmaf(g[q][0], w0 * e00, acc0);
                acc0 = fmaf(g[q][1], w1 * e01, acc0);
                acc1 = fmaf(g[q][2], w0 * e10, acc1);
                acc1 = fmaf(g[q][3], w1 * e11, acc1);
            }
            acc0 += __shfl_xor_sync(0xffffffffu, acc0, 1);
            acc0 += __shfl_xor_sync(0xffffffffu, acc0, 2);
            acc1 += __shfl_xor_sync(0xffffffffu, acc1, 1);
            acc1 += __shfl_xor_sync(0xffffffffu, acc1, 2);
            if (lc == 0) { sm[SYD_O + l0] = acc0; sm[SYD_O + l1] = acc1; }
        } else if (tid < 64) {
            int i = tid & 15, part = tid >> 4;
            float acc2 = 0.f;
#pragma unroll
            for (int q = 0; q < 16; ++q) {
                int l = part * 16 + q;
                acc2 = fmaf(sm[SB_O + l * 17 + i], sm[SWS_O + l] * sm[SDEC_O + l], acc2);
            }
            sm[SSR_O + tid] = acc2;
        }
        __syncthreads();

        // ---- phase 3: finalize chunk ----
        if (tid < 64) {
            int t = chunk * 64 + tid;
            float dx   = sm[SDX_O + tid];
            float base = sm[SYD_O + tid] + rb + (dx >= 0.f ? dx : 0.01f * dx);
            g_base[t * 64 + n] = base;
            g_cum[t * 64 + n]  = sm[SCUM_O + tid];
        } else if (tid < 80) {
            int i = tid - 64;
            g_sr[(n * 64 + chunk) * 16 + i] = sm[SSR_O + i] + sm[SSR_O + 16 + i]
                                            + sm[SSR_O + 32 + i] + sm[SSR_O + 48 + i];
        }
        __syncthreads();
    }
}

// ---------- K2: inter-chunk recurrence ----------
__global__ void k_scan() {
    __shared__ float ssr[64 * 16];
    __shared__ float sdc[64];
    const int n = blockIdx.x, tid = threadIdx.x;
    for (int i = tid; i < 1024; i += 64) ssr[i] = g_sr[n * 1024 + i];
    sdc[tid] = g_dch[n * 64 + tid];
    __syncthreads();
    if (tid < 16) {
        float h = 0.f;
        for (int c = 0; c < 64; ++c) {
            g_hr[(c * 64 + n) * 16 + tid] = h;
            h = sdc[c] * h + ssr[c * 16 + tid];
        }
    }
}

// ---------- K3: out = base + exp(cum) * (C . hr), fp16 C ----------
__global__ __launch_bounds__(256) void k_final(float* __restrict__ out) {
    __shared__ float hr[1024];
    const int chunk = blockIdx.x;
    const int lg = blockIdx.y;            // 0..15
    const int tid = threadIdx.x;
    for (int i = tid; i < 1024; i += 256) hr[i] = g_hr[chunk * 1024 + i];
    __syncthreads();
    const int nn = tid & 63;
    const int l = lg * 4 + (tid >> 6);
    const int t = chunk * 64 + l;
    const __half2* Cp = (const __half2*)(g_Ch + (t * 64 + nn) * 16);
    const float* h = hr + nn * 16;
    float acc = 0.f;
#pragma unroll
    for (int i2 = 0; i2 < 8; ++i2) {
        float2 c = __half22float2(Cp[i2]);
        acc = fmaf(c.x, h[2 * i2], acc);
        acc = fmaf(c.y, h[2 * i2 + 1], acc);
    }
    out[t * 64 + nn] = g_base[t * 64 + nn] + __expf(g_cum[t * 64 + nn]) * acc;
}

// ---------- launch ----------
extern "C" void kernel_launch(void* const* d_in, const int* in_sizes, int n_in,
                              void* d_out, int out_size) {
    const float* x        = (const float*)d_in[0];
    const float* conv_w   = (const float*)d_in[1];
    const float* conv_b   = (const float*)d_in[2];
    const float* pass_w   = (const float*)d_in[3];
    const float* pass_b   = (const float*)d_in[4];
    const float* red_w    = (const float*)d_in[5];
    const float* red_b    = (const float*)d_in[6];
    const float* dt_param = (const float*)d_in[7];
    float* out = (float*)d_out;

    int sms = 148;
    cudaDeviceGetAttribute(&sms, cudaDevAttrMultiProcessorCount, 0);
    const int nblocks = 2 * sms;

    const int smem_bytes = SMEMF * (int)sizeof(float);
    cudaFuncSetAttribute(k_main, cudaFuncAttributeMaxDynamicSharedMemorySize, smem_bytes);

    k_wt<<<(104 * 328 + 255) / 256, 256>>>(conv_w);
    k_main<<<nblocks, 256, smem_bytes>>>(x, conv_b, pass_w, pass_b,
                                         red_w, red_b, dt_param);
    k_scan<<<NSEQ, 64>>>();
    k_final<<<dim3(NCHUNK, 16), 256>>>(out);
}

// round 16
// speedup vs baseline: 1.0318x; 1.0318x over previous
#include <cuda_runtime.h>
#include <cuda_fp16.h>
#include <math.h>

// T=4096, B=4, S=16 -> 64 sequences; F=64, CH=97 (16 B + 16 C + 1 A + 64 X),
// K=5, CHUNK=64, 64 chunks, N_state=16, P=64 (collapsed via red_w projection).
// R10 base (persistent fp16-MMA conv, scalar fragment loads, Gram in MMA regs,
// 2 blocks/SM, fp16 g_C) + vectorized C export (stride-24 fp16 tiles) + phase-3
// eliminated (4 barriers/unit).

#define NSEQ   64
#define T_TOT  4096
#define NCHUNK 64

__device__ __forceinline__ float clip20(float v) { return fminf(fmaxf(v, -20.f), 20.f); }

// ---------- device scratch ----------
__device__ __align__(16) __half g_wB16[104 * 328];  // [ch][kk=k*64+f] fp16, zero-padded
__device__ __align__(16) __half g_Ch[T_TOT * NSEQ * 16]; // [t][n][16] fp16
__device__ float g_cum[T_TOT * NSEQ];               // [t][n]
__device__ float g_base[T_TOT * NSEQ];              // [t][n]
__device__ float g_sr[NSEQ * NCHUNK * 16];
__device__ float g_dch[NSEQ * NCHUNK];
__device__ float g_hr[NCHUNK * NSEQ * 16];          // [c][n][16]

// ---------- K0: build fp16 weight matrix ----------
__global__ void k_wt(const float* __restrict__ w) {
    int i = blockIdx.x * blockDim.x + threadIdx.x;
    if (i < 104 * 328) {
        int ch = i / 328, kk = i % 328;
        int k = kk >> 6, f = kk & 63;
        float v = (ch < 97 && kk < 320) ? w[ch * 320 + f * 5 + k] : 0.f;
        g_wB16[i] = __float2half(v);
    }
}

// ---------- shared layout (float offsets; fp16 regions via casts) ----------
#define WB16_O  0          // 104*328 halves = 17056 floats
#define XT_O    17056      // 68*72 halves = 2448 floats (x fp16, [lt][f] stride 72)
#define SX_O    19504      // 64*65 fp32 X channels
#define SC_O    23664      // 64*17 fp32
#define SB_O    24752      // 64*17 fp32
#define SB16_O  25840      // 64*24 halves = 768 floats (48B rows, 16B aligned)
#define SC16_O  26608      // 768
#define SA_O    27376      // 64
#define SCOEF_O 27440
#define SCUM_O  27504
#define SWS_O   27568
#define SDEC_O  27632
#define SDX_O   27696
#define SRW_O   27760
#define SPW_O   27824
#define SCB_O   27888      // 104
#define SMEMF   27992      // 111968 bytes -> 2 blocks/SM

#define MMA16(d, a0,a1,a2,a3, b0,b1) \
    asm volatile("mma.sync.aligned.m16n8k16.row.col.f32.f16.f16.f32 " \
        "{%0,%1,%2,%3},{%4,%5,%6,%7},{%8,%9},{%0,%1,%2,%3};" \
        : "+f"((d)[0]), "+f"((d)[1]), "+f"((d)[2]), "+f"((d)[3]) \
        : "r"(a0), "r"(a1), "r"(a2), "r"(a3), "r"(b0), "r"(b1))

// ---------- K1: persistent ----------
__global__ __launch_bounds__(256, 2) void k_main(
    const float* __restrict__ x,
    const float* __restrict__ conv_b,
    const float* __restrict__ pass_w,
    const float* __restrict__ pass_b,
    const float* __restrict__ red_w,
    const float* __restrict__ red_b,
    const float* __restrict__ dt_param)
{
    extern __shared__ float sm[];
    const int tid  = threadIdx.x;
    const int lane = tid & 31;
    const int wid  = tid >> 5;          // 8 warps

    // weight tile (fp16) + small params: ONCE per persistent block
    for (int i = tid; i < 17056 / 4; i += 256)
        ((float4*)sm)[i] = ((const float4*)g_wB16)[i];
    if (tid < 64) { sm[SRW_O + tid] = red_w[tid]; sm[SPW_O + tid] = pass_w[tid]; }
    if (tid >= 64 && tid < 168) sm[SCB_O + (tid - 64)] = (tid - 64 < 97) ? conv_b[tid - 64] : 0.f;
    const float dt = log1pf(expf(dt_param[0])) + 0.01f;
    const float pb = pass_b[0], rb = red_b[0];
    __syncthreads();

    // conv roles: mtile = wid&3 (16 t rows), nhalf = wid>>2
    const int mtile = wid & 3;
    const int nhalf = wid >> 2;
    const int nq    = nhalf ? 6 : 7;
    const int qb    = nhalf * 7;
    const int lc = lane & 3, lr = lane >> 2;

    __half* xt   = (__half*)(sm + XT_O);
    __half* b16h = (__half*)(sm + SB16_O);
    __half* c16h = (__half*)(sm + SC16_O);
    const __half* wb = (const __half*)sm;

    for (int u = blockIdx.x; u < NSEQ * NCHUNK; u += gridDim.x) {
        const int n = u & 63, chunk = u >> 6;
        const int b = n >> 4, s = n & 15;
        const int t0g = chunk * 64 - 4;

        // load x -> fp16 tile
        for (int i = tid; i < 68 * 64; i += 256) {
            int lt = i >> 6, f = i & 63;
            int tg = t0g + lt;
            float v = (tg >= 0) ? x[((tg * 4 + b) * 16 + s) * 64 + f] : 0.f;
            xt[lt * 72 + f] = __float2half(v);
        }
        __syncthreads();

        // ---- conv MMA (fp16 m16n8k16): 20 k-steps, scalar fragment loads ----
        float acc[7][4];
#pragma unroll
        for (int q = 0; q < 7; ++q)
#pragma unroll
            for (int e = 0; e < 4; ++e) acc[q][e] = 0.f;

        for (int ks = 0; ks < 20; ++ks) {
            const int kk0 = ks * 16;
            const int sh = kk0 >> 6, f0 = kk0 & 63;
            const __half* ap = xt + (mtile * 16 + lr + sh) * 72 + f0 + 2 * lc;
            unsigned a0 = *(const unsigned*)(ap);
            unsigned a1 = *(const unsigned*)(ap + 8 * 72);
            unsigned a2 = *(const unsigned*)(ap + 8);
            unsigned a3 = *(const unsigned*)(ap + 8 * 72 + 8);
            const __half* bp = wb + (qb * 8 + lr) * 328 + kk0 + 2 * lc;
#pragma unroll
            for (int qq = 0; qq < 7; ++qq) {
                if (qq < nq) {
                    unsigned b0 = *(const unsigned*)(bp + qq * 8 * 328);
                    unsigned b1 = *(const unsigned*)(bp + qq * 8 * 328 + 8);
                    MMA16(acc[qq], a0, a1, a2, a3, b0, b1);
                }
            }
        }

        // ---- epilogue: bias + (v + sigmoid(v)) + scatter ----
#pragma unroll
        for (int qq = 0; qq < 7; ++qq) {
            if (qq < nq) {
                const int ch0 = (qb + qq) * 8 + 2 * lc;
                const int t0r = mtile * 16 + lr;
#pragma unroll
                for (int e = 0; e < 4; ++e) {
                    const int ch = ch0 + (e & 1);
                    const int t  = t0r + (e >> 1) * 8;
                    float v = acc[qq][e] + sm[SCB_O + ch];
                    float uu = v + __fdividef(1.f, 1.f + __expf(-v));
                    if (ch < 16) {
                        sm[SB_O + t * 17 + ch] = uu;
                        b16h[t * 24 + ch] = __float2half(uu);
                    } else if (ch < 32) {
                        sm[SC_O + t * 17 + (ch - 16)] = uu;
                        c16h[t * 24 + (ch - 16)] = __float2half(uu);
                    } else if (ch == 32) {
                        float A  = -fabsf(uu);
                        float la = dt * A;
                        sm[SA_O + t]    = la;
                        sm[SCOEF_O + t] = (__expf(la) - 1.f) / (A + 1e-9f);
                    } else if (ch < 97) sm[SX_O + t * 65 + (ch - 33)] = uu;
                }
            }
        }
        __syncthreads();

        // ---- phase 1: scan(+cum export) | xr/Dx | C export (uint4) | Gram MMA ----
        float g[8][4];
        if (tid < 32) {
            float v0 = sm[SA_O + tid], v1 = sm[SA_O + 32 + tid];
#pragma unroll
            for (int o = 1; o < 32; o <<= 1) {
                float a0 = __shfl_up_sync(0xffffffffu, v0, o);
                float a1 = __shfl_up_sync(0xffffffffu, v1, o);
                if (tid >= o) { v0 += a0; v1 += a1; }
            }
            float tot0  = __shfl_sync(0xffffffffu, v0, 31);
            float cum_b = v1 + tot0;
            float tot   = __shfl_sync(0xffffffffu, cum_b, 31);
            sm[SCUM_O + tid]      = v0;
            sm[SCUM_O + 32 + tid] = cum_b;
            sm[SDEC_O + tid]      = __expf(clip20(tot - v0));
            sm[SDEC_O + 32 + tid] = __expf(clip20(tot - cum_b));
            g_cum[(chunk * 64 + tid) * 64 + n]      = v0;
            g_cum[(chunk * 64 + 32 + tid) * 64 + n] = cum_b;
            if (tid == 31) g_dch[n * 64 + chunk] = __expf(clip20(tot));
        } else if (tid < 96) {
            int t = tid - 32;
            float xr = 0.f;
#pragma unroll
            for (int p = 0; p < 64; ++p) xr = fmaf(sm[SX_O + t * 65 + p], sm[SRW_O + p], xr);
            const __half2* xrow = (const __half2*)(xt + (t + 4) * 72);
            float dx = pb;
#pragma unroll
            for (int f2 = 0; f2 < 32; ++f2) {
                float2 v = __half22float2(xrow[f2]);
                dx = fmaf(v.x, sm[SPW_O + 2 * f2], dx);
                dx = fmaf(v.y, sm[SPW_O + 2 * f2 + 1], dx);
            }
            sm[SWS_O + t] = xr * sm[SCOEF_O + t];
            sm[SDX_O + t] = dx;
        } else if (tid < 128) {
            // vectorized C export: 2 rows/thread, 2 x uint4 each
            int l = tid - 96;
#pragma unroll
            for (int rep = 0; rep < 2; ++rep) {
                int lr2 = l + rep * 32;
                const uint4* s4 = (const uint4*)(c16h + lr2 * 24);
                uint4* d4 = (uint4*)(g_Ch + (((chunk * 64 + lr2) * 64) + n) * 16);
                d4[0] = s4[0]; d4[1] = s4[1];
            }
        } else {
            // Gram: G[l][m] = sum_i C[l][i]*B[m][i]; warp w = l-tile, 8 m-tiles
            const int w = wid - 4;
            const __half* capt = c16h + (w * 16 + lr) * 24 + 2 * lc;
            unsigned a0 = *(const unsigned*)(capt);
            unsigned a1 = *(const unsigned*)(capt + 8 * 24);
            unsigned a2 = *(const unsigned*)(capt + 8);
            unsigned a3 = *(const unsigned*)(capt + 8 * 24 + 8);
#pragma unroll
            for (int q = 0; q < 8; ++q) {
                const __half* bq = b16h + (q * 8 + lr) * 24 + 2 * lc;
                unsigned b0 = *(const unsigned*)(bq);
                unsigned b1 = *(const unsigned*)(bq + 8);
                g[q][0] = g[q][1] = g[q][2] = g[q][3] = 0.f;
                MMA16(g[q], a0, a1, a2, a3, b0, b1);
            }
        }
        __syncthreads();

        // ---- phase 2: y_diag -> g_base (Gram warps) | full sr (tid 32..47) ----
        if (tid >= 128) {
            const int w = wid - 4;
            const int l0 = w * 16 + lr, l1 = l0 + 8;
            const float cl0 = sm[SCUM_O + l0], cl1 = sm[SCUM_O + l1];
            float acc0 = 0.f, acc1 = 0.f;
#pragma unroll
            for (int q = 0; q < 8; ++q) {
                const int m0 = q * 8 + 2 * lc, m1 = m0 + 1;
                const float w0 = sm[SWS_O + m0], w1 = sm[SWS_O + m1];
                const float c0 = sm[SCUM_O + m0], c1 = sm[SCUM_O + m1];
                float e00 = (m0 <= l0) ? __expf(clip20(cl0 - c0)) : 0.f;
                float e01 = (m1 <= l0) ? __expf(clip20(cl0 - c1)) : 0.f;
                float e10 = (m0 <= l1) ? __expf(clip20(cl1 - c0)) : 0.f;
                float e11 = (m1 <= l1) ? __expf(clip20(cl1 - c1)) : 0.f;
                acc0 = fmaf(g[q][0], w0 * e00, acc0);
                acc0 = fmaf(g[q][1], w1 * e01, acc0);
                acc1 = fmaf(g[q][2], w0 * e10, acc1);
                acc1 = fmaf(g[q][3], w1 * e11, acc1);
            }
            acc0 += __shfl_xor_sync(0xffffffffu, acc0, 1);
            acc0 += __shfl_xor_sync(0xffffffffu, acc0, 2);
            acc1 += __shfl_xor_sync(0xffffffffu, acc1, 1);
            acc1 += __shfl_xor_sync(0xffffffffu, acc1, 2);
            if (lc == 0) {
                float dx0 = sm[SDX_O + l0];
                g_base[(chunk * 64 + l0) * 64 + n] = acc0 + rb + (dx0 >= 0.f ? dx0 : 0.01f * dx0);
                float dx1 = sm[SDX_O + l1];
                g_base[(chunk * 64 + l1) * 64 + n] = acc1 + rb + (dx1 >= 0.f ? dx1 : 0.01f * dx1);
            }
        } else if (tid >= 32 && tid < 48) {
            const int i = tid - 32;
            float acc2 = 0.f;
#pragma unroll 8
            for (int l = 0; l < 64; ++l)
                acc2 = fmaf(sm[SB_O + l * 17 + i], sm[SWS_O + l] * sm[SDEC_O + l], acc2);
            g_sr[(n * 64 + chunk) * 16 + i] = acc2;
        }
        __syncthreads();
    }
}

// ---------- K2: inter-chunk recurrence ----------
__global__ void k_scan() {
    __shared__ float ssr[64 * 16];
    __shared__ float sdc[64];
    const int n = blockIdx.x, tid = threadIdx.x;
    for (int i = tid; i < 1024; i += 64) ssr[i] = g_sr[n * 1024 + i];
    sdc[tid] = g_dch[n * 64 + tid];
    __syncthreads();
    if (tid < 16) {
        float h = 0.f;
        for (int c = 0; c < 64; ++c) {
            g_hr[(c * 64 + n) * 16 + tid] = h;
            h = sdc[c] * h + ssr[c * 16 + tid];
        }
    }
}

// ---------- K3: out = base + exp(cum) * (C . hr), fp16 C ----------
__global__ __launch_bounds__(256) void k_final(float* __restrict__ out) {
    __shared__ float hr[1024];
    const int chunk = blockIdx.x;
    const int lg = blockIdx.y;            // 0..15
    const int tid = threadIdx.x;
    for (int i = tid; i < 1024; i += 256) hr[i] = g_hr[chunk * 1024 + i];
    __syncthreads();
    const int nn = tid & 63;
    const int l = lg * 4 + (tid >> 6);
    const int t = chunk * 64 + l;
    const __half2* Cp = (const __half2*)(g_Ch + (t * 64 + nn) * 16);
    const float* h = hr + nn * 16;
    float acc = 0.f;
#pragma unroll
    for (int i2 = 0; i2 < 8; ++i2) {
        float2 c = __half22float2(Cp[i2]);
        acc = fmaf(c.x, h[2 * i2], acc);
        acc = fmaf(c.y, h[2 * i2 + 1], acc);
    }
    out[t * 64 + nn] = g_base[t * 64 + nn] + __expf(g_cum[t * 64 + nn]) * acc;
}

// ---------- launch ----------
extern "C" void kernel_launch(void* const* d_in, const int* in_sizes, int n_in,
                              void* d_out, int out_size) {
    const float* x        = (const float*)d_in[0];
    const float* conv_w   = (const float*)d_in[1];
    const float* conv_b   = (const float*)d_in[2];
    const float* pass_w   = (const float*)d_in[3];
    const float* pass_b   = (const float*)d_in[4];
    const float* red_w    = (const float*)d_in[5];
    const float* red_b    = (const float*)d_in[6];
    const float* dt_param = (const float*)d_in[7];
    float* out = (float*)d_out;

    int sms = 148;
    cudaDeviceGetAttribute(&sms, cudaDevAttrMultiProcessorCount, 0);
    const int nblocks = 2 * sms;

    const int smem_bytes = SMEMF * (int)sizeof(float);
    cudaFuncSetAttribute(k_main, cudaFuncAttributeMaxDynamicSharedMemorySize, smem_bytes);

    k_wt<<<(104 * 328 + 255) / 256, 256>>>(conv_w);
    k_main<<<nblocks, 256, smem_bytes>>>(x, conv_b, pass_w, pass_b,
                                         red_w, red_b, dt_param);
    k_scan<<<NSEQ, 64>>>();
    k_final<<<dim3(NCHUNK, 16), 256>>>(out);
}